// round 16
// baseline (speedup 1.0000x reference)
#include <cuda_runtime.h>
#include <cuda_fp16.h>

#define NHID 32

// fp32 folded coefficients (tail path): per j: 9 K coeffs + W2[j][0..1] + pad
__device__ float g_const[NHID * 12];
// Main-GEMM B fragments for mma.sync.m16n8k16 (single k-step):
// [ntile][reg][lane]; KK rows 0-8 = f16(K), rows 9-15 = 0.
__device__ unsigned int g_Bfrag[4][2][32];
// Epilogue B2 fragments, hi and lo parts: [kstep][reg][lane]. B2 is 16x8:
// hi: n 0,1 = f16(W2[:,n]), n>=2 = 0
// lo: n 0,1 = f16((W2[:,n] - f16(W2[:,n])) * 4096), n>=2 = 0
__device__ unsigned int g_B2hi[2][2][32];
__device__ unsigned int g_B2lo[2][2][32];

struct cpx { float x, y; };

__device__ __forceinline__ void apply1q(cpx* s, cpx m00, cpx m01, cpx m10, cpx m11, int wire)
{
    int st = 1 << (2 - wire);
    for (int i = 0; i < 8; i++) {
        if (i & st) continue;
        cpx a = s[i], b = s[i + st];
        cpx n0 = { m00.x*a.x - m00.y*a.y + m01.x*b.x - m01.y*b.y,
                   m00.x*a.y + m00.y*a.x + m01.x*b.y + m01.y*b.x };
        cpx n1 = { m10.x*a.x - m10.y*a.y + m11.x*b.x - m11.y*b.y,
                   m10.x*a.y + m10.y*a.x + m11.x*b.y + m11.y*b.x };
        s[i] = n0; s[i + st] = n1;
    }
}

__device__ __forceinline__ void applyCRX(cpx* s, float c, float sn, int ctrl, int tgt)
{
    int cs = 1 << (2 - ctrl), ts = 1 << (2 - tgt);
    for (int i = 0; i < 8; i++) {
        if (!(i & cs) || (i & ts)) continue;
        cpx a = s[i], b = s[i + ts];
        s[i]      = { c*a.x + sn*b.y, c*a.y - sn*b.x };
        s[i + ts] = { c*b.x + sn*a.y, c*b.y - sn*a.x };
    }
}

__global__ void setup_kernel(const float* __restrict__ theta,
                             const float* __restrict__ W1,
                             const float* __restrict__ b1,
                             const float* __restrict__ W2)
{
    __shared__ cpx Vs[4][8];
    int tid = threadIdx.x;

    if (tid < 4) {
        cpx s[8];
        for (int i = 0; i < 8; i++) s[i] = {0.f, 0.f};
        s[tid * 2] = {1.f, 0.f};
        float c, sn;
        __sincosf(0.5f * theta[0], &sn, &c);
        apply1q(s, {c,0.f},{0.f,-sn},{0.f,-sn},{c,0.f}, 0);
        __sincosf(0.5f * theta[1], &sn, &c);
        apply1q(s, {c,0.f},{-sn,0.f},{sn,0.f},{c,0.f}, 1);
        __sincosf(0.5f * theta[2], &sn, &c);
        apply1q(s, {c,-sn},{0.f,0.f},{0.f,0.f},{c,sn}, 2);
        __sincosf(0.5f * theta[3], &sn, &c);
        applyCRX(s, c, sn, 0, 1);
        __sincosf(0.5f * theta[4], &sn, &c);
        apply1q(s, {c,0.f},{-sn,0.f},{sn,0.f},{c,0.f}, 2);
        __sincosf(0.5f * theta[5], &sn, &c);
        apply1q(s, {c,0.f},{0.f,-sn},{0.f,-sn},{c,0.f}, 1);
        __sincosf(0.5f * theta[6], &sn, &c);
        applyCRX(s, c, sn, 1, 2);
        __sincosf(0.5f * theta[7], &sn, &c);
        apply1q(s, {c,-sn},{0.f,0.f},{0.f,0.f},{c,sn}, 0);
        for (int k = 0; k < 8; k++)
            Vs[tid][k] = (tid >= 2) ? cpx{ s[k].y, -s[k].x } : s[k]; // * (-i)
    }
    __syncwarp();

    int j = tid;
    float M[4][4];
    for (int a = 0; a < 4; a++)
        for (int b = 0; b < 4; b++) {
            float m = 0.f;
            for (int k = 0; k < 8; k++)
                m += W1[k * NHID + j] * (Vs[a][k].x * Vs[b][k].x + Vs[a][k].y * Vs[b][k].y);
            M[a][b] = m;
        }

    const float R[2][2][3] = { { {0.5f, 0.5f, 0.f}, {0.f, 0.f, 0.5f} },
                               { {0.f, 0.f, 0.5f}, {0.5f, -0.5f, 0.f} } };
    float K[3][3] = { {0.f,0.f,0.f},{0.f,0.f,0.f},{0.f,0.f,0.f} };
    for (int a = 0; a < 4; a++)
        for (int b = 0; b < 4; b++) {
            int ia = a >> 1, ja = a & 1, ib = b >> 1, jb = b & 1;
            float Mab = M[a][b];
            for (int m = 0; m < 3; m++)
                for (int n = 0; n < 3; n++)
                    K[m][n] += Mab * R[ia][ib][m] * R[ja][jb][n];
        }
    K[0][0] += b1[j];

    float cf[9];
    for (int t = 0; t < 9; t++) cf[t] = K[t / 3][t % 3];

    for (int t = 0; t < 9; t++) g_const[j * 12 + t] = cf[t];
    g_const[j * 12 + 9]  = W2[j * 2 + 0];
    g_const[j * 12 + 10] = W2[j * 2 + 1];
    g_const[j * 12 + 11] = 0.f;

    // main-GEMM fragments: single k-step, B = f16(K), rows 9-15 zero
    {
        int nt = j >> 3, g = j & 7;
        for (int r = 0; r < 2; r++)
            for (int t = 0; t < 4; t++) {
                int r0 = 2 * t + r * 8;
                float v0 = (r0     < 9) ? cf[r0]     : 0.f;
                float v1 = (r0 + 1 < 9) ? cf[r0 + 1] : 0.f;
                __half2 h2 = __floats2half2_rn(v0, v1);
                g_Bfrag[nt][r][g * 4 + t] = *reinterpret_cast<unsigned int*>(&h2);
            }
    }

    // epilogue B2 fragments: hi/lo split in separate fragment sets (n=0,1 only)
    {
        int g = tid >> 2, t = tid & 3;
        for (int ks = 0; ks < 2; ks++)
            for (int r = 0; r < 2; r++) {
                int k0 = ks * 16 + 2 * t + r * 8;
                float h0 = 0.f, h1 = 0.f, l0 = 0.f, l1 = 0.f;
                if (g < 2) {
                    float w0f = W2[k0 * 2 + g];
                    float w1f = W2[(k0 + 1) * 2 + g];
                    h0 = __half2float(__float2half_rn(w0f));
                    h1 = __half2float(__float2half_rn(w1f));
                    l0 = (w0f - h0) * 4096.f;
                    l1 = (w1f - h1) * 4096.f;
                }
                __half2 hh = __floats2half2_rn(h0, h1);
                __half2 hl = __floats2half2_rn(l0, l1);
                g_B2hi[ks][r][tid] = *reinterpret_cast<unsigned int*>(&hh);
                g_B2lo[ks][r][tid] = *reinterpret_cast<unsigned int*>(&hl);
            }
    }
}

__device__ __forceinline__ void mma16816(float c[4],
                                         unsigned a0, unsigned a1, unsigned a2, unsigned a3,
                                         unsigned b0, unsigned b1)
{
    asm volatile(
        "mma.sync.aligned.m16n8k16.row.col.f32.f16.f16.f32 "
        "{%0,%1,%2,%3}, {%4,%5,%6,%7}, {%8,%9}, {%0,%1,%2,%3};"
        : "+f"(c[0]), "+f"(c[1]), "+f"(c[2]), "+f"(c[3])
        : "r"(a0), "r"(a1), "r"(a2), "r"(a3), "r"(b0), "r"(b1));
}

__device__ __forceinline__ void ldmatrix_x4(unsigned& a0, unsigned& a1,
                                            unsigned& a2, unsigned& a3,
                                            unsigned saddr)
{
    asm volatile(
        "ldmatrix.sync.aligned.m8n8.x4.shared.b16 {%0,%1,%2,%3}, [%4];"
        : "=r"(a0), "=r"(a1), "=r"(a2), "=r"(a3) : "r"(saddr));
}

// Persistent warps: each warp grid-strides over 64-sample groups, paying
// uniform loads once. Hidden layer: f16 MMA (A=f16(F), B=f16(K)). Output
// layer: dual-accumulator MMA epilogue (exact W2 = hi + lo*2^-12, no shfl).
#define ROWH 24   // 48 B row stride: uint4-aligned, bank-conflict-free
__global__ void __launch_bounds__(256, 4)
qmlp_mma(const float* __restrict__ x,
         const float* __restrict__ b2,
         float* __restrict__ out, int B)
{
    __shared__ __align__(16) __half sA[8][2][32 * ROWH];

    int lane = threadIdx.x & 31;
    int warp = threadIdx.x >> 5;
    int gwarp = blockIdx.x * 8 + warp;
    int nwarps = gridDim.x * 8;
    int ngroups = (B + 63) / 64;

    int g = lane >> 2, t = lane & 3;
    float bias0 = __ldg(&b2[0]);
    float bias1 = __ldg(&b2[1]);

    // hoisted uniform fragments (once per warp lifetime)
    unsigned bf[4][2];
    #pragma unroll
    for (int nt = 0; nt < 4; nt++) {
        bf[nt][0] = __ldg(&g_Bfrag[nt][0][lane]);
        bf[nt][1] = __ldg(&g_Bfrag[nt][1][lane]);
    }
    unsigned b2h[2][2], b2l[2][2];
    #pragma unroll
    for (int ks = 0; ks < 2; ks++) {
        b2h[ks][0] = __ldg(&g_B2hi[ks][0][lane]);
        b2h[ks][1] = __ldg(&g_B2hi[ks][1][lane]);
        b2l[ks][0] = __ldg(&g_B2lo[ks][0][lane]);
        b2l[ks][1] = __ldg(&g_B2lo[ks][1][lane]);
    }

    // pre-zero pad columns 8-15 of both buffers (col 8 rewritten per group)
    *reinterpret_cast<uint4*>(&sA[warp][0][lane * ROWH + 8]) = make_uint4(0,0,0,0);
    *reinterpret_cast<uint4*>(&sA[warp][1][lane * ROWH + 8]) = make_uint4(0,0,0,0);

    int lm_row   = lane & 15;
    int lm_khalf = (lane >> 4) * 8;

    const __half2 hz = __floats2half2_rn(0.f, 0.f);
    const float SCL = 1.f / 4096.f;

    for (int grp = gwarp; grp < ngroups; grp += nwarps) {
        long long wbase = (long long)grp * 64;

        if (wbase + 64 <= B) {
            // ---- stage BOTH 32-sample halves, then one syncwarp ----
            __syncwarp();   // prior group's LDSM done before overwrite
            #pragma unroll
            for (int it = 0; it < 2; it++) {
                long long S = wbase + (long long)it * 32 + lane;
                float xa = __ldg(&x[S * 3]);
                float xb = __ldg(&x[S * 3 + 1]);   // x[...+2] is a global phase
                float s0n, c0n, s1n, c1n;
                __sincosf(xa, &s0n, &c0n);
                __sincosf(xb, &s1n, &c1n);

                __half2 h2;
                unsigned w0, w1, w2, w3, w4;
                #define PACK(a, b) (h2 = __floats2half2_rn((a), (b)), *reinterpret_cast<unsigned*>(&h2))
                w0 = PACK(1.f, c1n);
                w1 = PACK(s1n, c0n);
                w2 = PACK(c0n * c1n, c0n * s1n);
                w3 = PACK(s0n, s0n * c1n);
                w4 = PACK(s0n * s1n, 0.f);
                #undef PACK

                __half* row = &sA[warp][it][lane * ROWH];
                *reinterpret_cast<uint4*>(row) = make_uint4(w0, w1, w2, w3);
                *reinterpret_cast<unsigned*>(row + 8) = w4;
            }
            __syncwarp();

            // ---- 4 independent tile chains ----
            #pragma unroll
            for (int it = 0; it < 2; it++) {
                unsigned sbase = (unsigned)__cvta_generic_to_shared(&sA[warp][it][0]);
                #pragma unroll
                for (int tile = 0; tile < 2; tile++) {
                    float acc[4][4];
                    #pragma unroll
                    for (int nt = 0; nt < 4; nt++)
                        #pragma unroll
                        for (int c = 0; c < 4; c++) acc[nt][c] = 0.f;

                    unsigned lmaddr = sbase +
                        ((unsigned)(tile * 16 + lm_row) * (unsigned)ROWH + (unsigned)lm_khalf) * 2u;
                    unsigned a0, a1, a2, a3;
                    ldmatrix_x4(a0, a1, a2, a3, lmaddr);
                    #pragma unroll
                    for (int nt = 0; nt < 4; nt++)
                        mma16816(acc[nt], a0, a1, a2, a3, bf[nt][0], bf[nt][1]);

                    // epilogue on the tensor pipe, dual accumulator (no shfl)
                    unsigned hp[4][2];
                    #pragma unroll
                    for (int nt = 0; nt < 4; nt++) {
                        __half2 t01 = __floats2half2_rn(acc[nt][0], acc[nt][1]);
                        __half2 t23 = __floats2half2_rn(acc[nt][2], acc[nt][3]);
                        t01 = __hmax2(t01, hz);
                        t23 = __hmax2(t23, hz);
                        hp[nt][0] = *reinterpret_cast<unsigned*>(&t01);
                        hp[nt][1] = *reinterpret_cast<unsigned*>(&t23);
                    }
                    float oh[4] = { 0.f, 0.f, 0.f, 0.f };
                    float ol[4] = { 0.f, 0.f, 0.f, 0.f };
                    mma16816(oh, hp[0][0], hp[0][1], hp[1][0], hp[1][1], b2h[0][0], b2h[0][1]);
                    mma16816(oh, hp[2][0], hp[2][1], hp[3][0], hp[3][1], b2h[1][0], b2h[1][1]);
                    mma16816(ol, hp[0][0], hp[0][1], hp[1][0], hp[1][1], b2l[0][0], b2l[0][1]);
                    mma16816(ol, hp[2][0], hp[2][1], hp[3][0], hp[3][1], b2l[1][0], b2l[1][1]);

                    if (t == 0) {
                        long long rr = wbase + (long long)it * 32 + tile * 16 + g;
                        float2* ov = reinterpret_cast<float2*>(out);
                        ov[rr]     = make_float2(fmaf(ol[0], SCL, oh[0]) + bias0,
                                                 fmaf(ol[1], SCL, oh[1]) + bias1);
                        ov[rr + 8] = make_float2(fmaf(ol[2], SCL, oh[2]) + bias0,
                                                 fmaf(ol[3], SCL, oh[3]) + bias1);
                    }
                }
            }
        } else {
            // scalar fp32 tail (partial last group)
            for (long long s = wbase + lane; s < B; s += 32) {
                float xx0 = x[s * 3], xx1 = x[s * 3 + 1];
                float cc0, ss0, cc1, ss1;
                __sincosf(xx0, &ss0, &cc0);
                __sincosf(xx1, &ss1, &cc1);
                float o0 = bias0, o1 = bias1;
                for (int j = 0; j < NHID; j++) {
                    const float* K = &g_const[j * 12];
                    float t0 = K[0] + K[1]*cc1 + K[2]*ss1;
                    float t1 = K[3] + K[4]*cc1 + K[5]*ss1;
                    float t2 = K[6] + K[7]*cc1 + K[8]*ss1;
                    float h = fmaxf(t0 + cc0*t1 + ss0*t2, 0.f);
                    o0 += h * K[9];
                    o1 += h * K[10];
                }
                out[s * 2]     = o0;
                out[s * 2 + 1] = o1;
            }
        }
    }
}

extern "C" void kernel_launch(void* const* d_in, const int* in_sizes, int n_in,
                              void* d_out, int out_size)
{
    const float* x     = (const float*)d_in[0];
    const float* theta = (const float*)d_in[1];
    const float* W1    = (const float*)d_in[2];
    const float* b1    = (const float*)d_in[3];
    const float* W2    = (const float*)d_in[4];
    const float* b2    = (const float*)d_in[5];
    int B = in_sizes[0] / 3;

    setup_kernel<<<1, 32>>>(theta, W1, b1, W2);

    // persistent: full residency = 148 SMs x 4 blocks
    int ngroups = (B + 63) / 64;
    int nwarps_needed = ngroups;               // one group per warp minimum
    int nblocks = (nwarps_needed + 7) / 8;
    if (nblocks > 592) nblocks = 592;
    qmlp_mma<<<nblocks, 256>>>(x, b2, (float*)d_out, B);
}

// round 17
// speedup vs baseline: 1.1052x; 1.1052x over previous
#include <cuda_runtime.h>
#include <cuda_fp16.h>

#define NHID 32

struct cpx { float x, y; };

__device__ __forceinline__ void apply1q(cpx* s, cpx m00, cpx m01, cpx m10, cpx m11, int wire)
{
    int st = 1 << (2 - wire);
    for (int i = 0; i < 8; i++) {
        if (i & st) continue;
        cpx a = s[i], b = s[i + st];
        cpx n0 = { m00.x*a.x - m00.y*a.y + m01.x*b.x - m01.y*b.y,
                   m00.x*a.y + m00.y*a.x + m01.x*b.y + m01.y*b.x };
        cpx n1 = { m10.x*a.x - m10.y*a.y + m11.x*b.x - m11.y*b.y,
                   m10.x*a.y + m10.y*a.x + m11.x*b.y + m11.y*b.x };
        s[i] = n0; s[i + st] = n1;
    }
}

__device__ __forceinline__ void applyCRX(cpx* s, float c, float sn, int ctrl, int tgt)
{
    int cs = 1 << (2 - ctrl), ts = 1 << (2 - tgt);
    for (int i = 0; i < 8; i++) {
        if (!(i & cs) || (i & ts)) continue;
        cpx a = s[i], b = s[i + ts];
        s[i]      = { c*a.x + sn*b.y, c*a.y - sn*b.x };
        s[i + ts] = { c*b.x + sn*a.y, c*b.y - sn*a.x };
    }
}

__device__ __forceinline__ void mma16816(float c[4],
                                         unsigned a0, unsigned a1, unsigned a2, unsigned a3,
                                         unsigned b0, unsigned b1)
{
    asm volatile(
        "mma.sync.aligned.m16n8k16.row.col.f32.f16.f16.f32 "
        "{%0,%1,%2,%3}, {%4,%5,%6,%7}, {%8,%9}, {%0,%1,%2,%3};"
        : "+f"(c[0]), "+f"(c[1]), "+f"(c[2]), "+f"(c[3])
        : "r"(a0), "r"(a1), "r"(a2), "r"(a3), "r"(b0), "r"(b1));
}

__device__ __forceinline__ void ldmatrix_x4(unsigned& a0, unsigned& a1,
                                            unsigned& a2, unsigned& a3,
                                            unsigned saddr)
{
    asm volatile(
        "ldmatrix.sync.aligned.m8n8.x4.shared.b16 {%0,%1,%2,%3}, [%4];"
        : "=r"(a0), "=r"(a1), "=r"(a2), "=r"(a3) : "r"(saddr));
}

// Single fused kernel. Warp 0 of each block rebuilds the folded-coefficient
// fragment tables in smem (once per block), then all warps run the
// persistent MMA loop. Hidden layer: f16 MMA (A=f16(F), B=f16(K)).
// Output layer: dual-accumulator MMA epilogue (exact W2 = hi + lo*2^-12).
#define ROWH 24   // 48 B row stride: uint4-aligned, bank-conflict-free
__global__ void __launch_bounds__(256, 4)
qmlp_fused(const float* __restrict__ x,
           const float* __restrict__ theta,
           const float* __restrict__ W1,
           const float* __restrict__ b1,
           const float* __restrict__ W2,
           const float* __restrict__ b2,
           float* __restrict__ out, int B)
{
    __shared__ __align__(16) __half sA[8][2][32 * ROWH];
    __shared__ cpx      sVs[4][8];
    __shared__ float    sCF[32][12];          // per j: cf[0..8], W2j0, W2j1, pad
    __shared__ unsigned sBfrag[4][2][32];
    __shared__ unsigned sB2hi[2][2][32];
    __shared__ unsigned sB2lo[2][2][32];

    int lane = threadIdx.x & 31;
    int warp = threadIdx.x >> 5;

    // ================= per-block setup (warp 0) =================
    if (warp == 0) {
        int tid = lane;
        if (tid < 4) {
            cpx s[8];
            for (int i = 0; i < 8; i++) s[i] = {0.f, 0.f};
            s[tid * 2] = {1.f, 0.f};
            float c, sn;
            __sincosf(0.5f * theta[0], &sn, &c);
            apply1q(s, {c,0.f},{0.f,-sn},{0.f,-sn},{c,0.f}, 0);
            __sincosf(0.5f * theta[1], &sn, &c);
            apply1q(s, {c,0.f},{-sn,0.f},{sn,0.f},{c,0.f}, 1);
            __sincosf(0.5f * theta[2], &sn, &c);
            apply1q(s, {c,-sn},{0.f,0.f},{0.f,0.f},{c,sn}, 2);
            __sincosf(0.5f * theta[3], &sn, &c);
            applyCRX(s, c, sn, 0, 1);
            __sincosf(0.5f * theta[4], &sn, &c);
            apply1q(s, {c,0.f},{-sn,0.f},{sn,0.f},{c,0.f}, 2);
            __sincosf(0.5f * theta[5], &sn, &c);
            apply1q(s, {c,0.f},{0.f,-sn},{0.f,-sn},{c,0.f}, 1);
            __sincosf(0.5f * theta[6], &sn, &c);
            applyCRX(s, c, sn, 1, 2);
            __sincosf(0.5f * theta[7], &sn, &c);
            apply1q(s, {c,-sn},{0.f,0.f},{0.f,0.f},{c,sn}, 0);
            for (int k = 0; k < 8; k++)
                sVs[tid][k] = (tid >= 2) ? cpx{ s[k].y, -s[k].x } : s[k]; // * (-i)
        }
        __syncwarp();

        int j = tid;
        // load W1 column j once
        float w1j[8];
        #pragma unroll
        for (int k = 0; k < 8; k++) w1j[k] = W1[k * NHID + j];

        float M[4][4];
        for (int a = 0; a < 4; a++)
            for (int b = 0; b < 4; b++) {
                float m = 0.f;
                for (int k = 0; k < 8; k++)
                    m += w1j[k] * (sVs[a][k].x * sVs[b][k].x + sVs[a][k].y * sVs[b][k].y);
                M[a][b] = m;
            }

        const float R[2][2][3] = { { {0.5f, 0.5f, 0.f}, {0.f, 0.f, 0.5f} },
                                   { {0.f, 0.f, 0.5f}, {0.5f, -0.5f, 0.f} } };
        float K[3][3] = { {0.f,0.f,0.f},{0.f,0.f,0.f},{0.f,0.f,0.f} };
        for (int a = 0; a < 4; a++)
            for (int b = 0; b < 4; b++) {
                int ia = a >> 1, ja = a & 1, ib = b >> 1, jb = b & 1;
                float Mab = M[a][b];
                for (int m = 0; m < 3; m++)
                    for (int n = 0; n < 3; n++)
                        K[m][n] += Mab * R[ia][ib][m] * R[ja][jb][n];
            }
        K[0][0] += b1[j];

        float cf[9];
        for (int t = 0; t < 9; t++) cf[t] = K[t / 3][t % 3];

        for (int t = 0; t < 9; t++) sCF[j][t] = cf[t];
        sCF[j][9]  = W2[j * 2 + 0];
        sCF[j][10] = W2[j * 2 + 1];
        sCF[j][11] = 0.f;
        __syncwarp();   // sCF complete before cross-lane fragment builds

        // main-GEMM fragments: single k-step, B = f16(K), rows 9-15 zero.
        // lane (g,t) of ntile nt needs column j' = nt*8+g, rows 2t(+1)+8r.
        {
            int gg = tid >> 2, tt = tid & 3;
            #pragma unroll
            for (int nt = 0; nt < 4; nt++) {
                int jc = nt * 8 + gg;
                #pragma unroll
                for (int r = 0; r < 2; r++) {
                    int r0 = 2 * tt + r * 8;
                    float v0 = (r0     < 9) ? sCF[jc][r0]     : 0.f;
                    float v1 = (r0 + 1 < 9) ? sCF[jc][r0 + 1] : 0.f;
                    __half2 h2 = __floats2half2_rn(v0, v1);
                    sBfrag[nt][r][tid] = *reinterpret_cast<unsigned*>(&h2);
                }
            }
        }

        // epilogue B2 fragments: hi/lo split (n=0,1 only)
        {
            int gg = tid >> 2, tt = tid & 3;
            #pragma unroll
            for (int ks = 0; ks < 2; ks++)
                #pragma unroll
                for (int r = 0; r < 2; r++) {
                    int k0 = ks * 16 + 2 * tt + r * 8;
                    float h0 = 0.f, h1 = 0.f, l0 = 0.f, l1 = 0.f;
                    if (gg < 2) {
                        float w0f = sCF[k0][9 + gg];
                        float w1f = sCF[k0 + 1][9 + gg];
                        h0 = __half2float(__float2half_rn(w0f));
                        h1 = __half2float(__float2half_rn(w1f));
                        l0 = (w0f - h0) * 4096.f;
                        l1 = (w1f - h1) * 4096.f;
                    }
                    __half2 hh = __floats2half2_rn(h0, h1);
                    __half2 hl = __floats2half2_rn(l0, l1);
                    sB2hi[ks][r][tid] = *reinterpret_cast<unsigned*>(&hh);
                    sB2lo[ks][r][tid] = *reinterpret_cast<unsigned*>(&hl);
                }
        }
    }
    __syncthreads();

    // ================= persistent MMA loop (all warps) =================
    int gwarp = blockIdx.x * 8 + warp;
    int nwarps = gridDim.x * 8;
    int ngroups = (B + 63) / 64;

    int g = lane >> 2, t = lane & 3;
    float bias0 = __ldg(&b2[0]);
    float bias1 = __ldg(&b2[1]);

    // hoist fragments from smem (once per warp lifetime)
    unsigned bf[4][2];
    #pragma unroll
    for (int nt = 0; nt < 4; nt++) {
        bf[nt][0] = sBfrag[nt][0][lane];
        bf[nt][1] = sBfrag[nt][1][lane];
    }
    unsigned b2h[2][2], b2l[2][2];
    #pragma unroll
    for (int ks = 0; ks < 2; ks++) {
        b2h[ks][0] = sB2hi[ks][0][lane];
        b2h[ks][1] = sB2hi[ks][1][lane];
        b2l[ks][0] = sB2lo[ks][0][lane];
        b2l[ks][1] = sB2lo[ks][1][lane];
    }

    // pre-zero pad columns 8-15 of both buffers (col 8 rewritten per group)
    *reinterpret_cast<uint4*>(&sA[warp][0][lane * ROWH + 8]) = make_uint4(0,0,0,0);
    *reinterpret_cast<uint4*>(&sA[warp][1][lane * ROWH + 8]) = make_uint4(0,0,0,0);

    int lm_row   = lane & 15;
    int lm_khalf = (lane >> 4) * 8;

    const __half2 hz = __floats2half2_rn(0.f, 0.f);
    const float SCL = 1.f / 4096.f;

    for (int grp = gwarp; grp < ngroups; grp += nwarps) {
        long long wbase = (long long)grp * 64;

        if (wbase + 64 <= B) {
            __syncwarp();   // prior group's LDSM done before overwrite
            #pragma unroll
            for (int it = 0; it < 2; it++) {
                long long S = wbase + (long long)it * 32 + lane;
                float xa = __ldg(&x[S * 3]);
                float xb = __ldg(&x[S * 3 + 1]);   // x[...+2] is a global phase
                float s0n, c0n, s1n, c1n;
                __sincosf(xa, &s0n, &c0n);
                __sincosf(xb, &s1n, &c1n);

                __half2 h2;
                unsigned w0, w1, w2, w3, w4;
                #define PACK(a, b) (h2 = __floats2half2_rn((a), (b)), *reinterpret_cast<unsigned*>(&h2))
                w0 = PACK(1.f, c1n);
                w1 = PACK(s1n, c0n);
                w2 = PACK(c0n * c1n, c0n * s1n);
                w3 = PACK(s0n, s0n * c1n);
                w4 = PACK(s0n * s1n, 0.f);
                #undef PACK

                __half* row = &sA[warp][it][lane * ROWH];
                *reinterpret_cast<uint4*>(row) = make_uint4(w0, w1, w2, w3);
                *reinterpret_cast<unsigned*>(row + 8) = w4;
            }
            __syncwarp();

            #pragma unroll
            for (int it = 0; it < 2; it++) {
                unsigned sbase = (unsigned)__cvta_generic_to_shared(&sA[warp][it][0]);
                #pragma unroll
                for (int tile = 0; tile < 2; tile++) {
                    float acc[4][4];
                    #pragma unroll
                    for (int nt = 0; nt < 4; nt++)
                        #pragma unroll
                        for (int c = 0; c < 4; c++) acc[nt][c] = 0.f;

                    unsigned lmaddr = sbase +
                        ((unsigned)(tile * 16 + lm_row) * (unsigned)ROWH + (unsigned)lm_khalf) * 2u;
                    unsigned a0, a1, a2, a3;
                    ldmatrix_x4(a0, a1, a2, a3, lmaddr);
                    #pragma unroll
                    for (int nt = 0; nt < 4; nt++)
                        mma16816(acc[nt], a0, a1, a2, a3, bf[nt][0], bf[nt][1]);

                    unsigned hp[4][2];
                    #pragma unroll
                    for (int nt = 0; nt < 4; nt++) {
                        __half2 t01 = __floats2half2_rn(acc[nt][0], acc[nt][1]);
                        __half2 t23 = __floats2half2_rn(acc[nt][2], acc[nt][3]);
                        t01 = __hmax2(t01, hz);
                        t23 = __hmax2(t23, hz);
                        hp[nt][0] = *reinterpret_cast<unsigned*>(&t01);
                        hp[nt][1] = *reinterpret_cast<unsigned*>(&t23);
                    }
                    float oh[4] = { 0.f, 0.f, 0.f, 0.f };
                    float ol[4] = { 0.f, 0.f, 0.f, 0.f };
                    mma16816(oh, hp[0][0], hp[0][1], hp[1][0], hp[1][1], b2h[0][0], b2h[0][1]);
                    mma16816(oh, hp[2][0], hp[2][1], hp[3][0], hp[3][1], b2h[1][0], b2h[1][1]);
                    mma16816(ol, hp[0][0], hp[0][1], hp[1][0], hp[1][1], b2l[0][0], b2l[0][1]);
                    mma16816(ol, hp[2][0], hp[2][1], hp[3][0], hp[3][1], b2l[1][0], b2l[1][1]);

                    if (t == 0) {
                        long long rr = wbase + (long long)it * 32 + tile * 16 + g;
                        float2* ov = reinterpret_cast<float2*>(out);
                        ov[rr]     = make_float2(fmaf(ol[0], SCL, oh[0]) + bias0,
                                                 fmaf(ol[1], SCL, oh[1]) + bias1);
                        ov[rr + 8] = make_float2(fmaf(ol[2], SCL, oh[2]) + bias0,
                                                 fmaf(ol[3], SCL, oh[3]) + bias1);
                    }
                }
            }
        } else {
            // scalar fp32 tail (partial last group)
            for (long long s = wbase + lane; s < B; s += 32) {
                float xx0 = x[s * 3], xx1 = x[s * 3 + 1];
                float cc0, ss0, cc1, ss1;
                __sincosf(xx0, &ss0, &cc0);
                __sincosf(xx1, &ss1, &cc1);
                float o0 = bias0, o1 = bias1;
                for (int j = 0; j < NHID; j++) {
                    const float* K = &sCF[j][0];
                    float t0 = K[0] + K[1]*cc1 + K[2]*ss1;
                    float t1 = K[3] + K[4]*cc1 + K[5]*ss1;
                    float t2 = K[6] + K[7]*cc1 + K[8]*ss1;
                    float h = fmaxf(t0 + cc0*t1 + ss0*t2, 0.f);
                    o0 += h * K[9];
                    o1 += h * K[10];
                }
                out[s * 2]     = o0;
                out[s * 2 + 1] = o1;
            }
        }
    }
}

extern "C" void kernel_launch(void* const* d_in, const int* in_sizes, int n_in,
                              void* d_out, int out_size)
{
    const float* x     = (const float*)d_in[0];
    const float* theta = (const float*)d_in[1];
    const float* W1    = (const float*)d_in[2];
    const float* b1    = (const float*)d_in[3];
    const float* W2    = (const float*)d_in[4];
    const float* b2    = (const float*)d_in[5];
    int B = in_sizes[0] / 3;

    int ngroups = (B + 63) / 64;
    int nblocks = (ngroups + 7) / 8;
    if (nblocks > 592) nblocks = 592;
    if (nblocks < 1) nblocks = 1;
    qmlp_fused<<<nblocks, 256>>>(x, theta, W1, b1, W2, b2, (float*)d_out, B);
}